// round 5
// baseline (speedup 1.0000x reference)
#include <cuda_runtime.h>
#include <cuda_fp16.h>
#include <cstdint>

// ---------------------------------------------------------------------------
// Problem geometry
// ---------------------------------------------------------------------------
#define OUT_DIM 11008
#define IN_DIM  4096
#define B_DIM   8192
#define N_ELEM  (OUT_DIM * IN_DIM)          // 45,088,768 weights
#define X_ELEM  (B_DIM * IN_DIM)            // 33,554,432 activations

// GEMM tiling: CTA 128x256, k-stage 32, 8 warps of 64x64
#define CTA_M 128
#define CTA_N 256
#define CTA_K 32
#define NSTAGE 4
#define NK_ITERS (IN_DIM / CTA_K)           // 128

#define A_STAGE_HALFS (CTA_M * CTA_K)       // 4096 halves = 8 KB
#define B_STAGE_HALFS (CTA_N * CTA_K)       // 8192 halves = 16 KB
#define SMEM_BYTES ((A_STAGE_HALFS + B_STAGE_HALFS) * NSTAGE * 2)   // 98304

// ---------------------------------------------------------------------------
// Static device scratch (harness-legal; no dynamic allocation)
// ---------------------------------------------------------------------------
__device__ __align__(1024) __half g_W[(size_t)OUT_DIM * IN_DIM];    // 90 MB
__device__ __align__(1024) __half g_X[(size_t)B_DIM * IN_DIM];      // 64 MB

// ---------------------------------------------------------------------------
// Dequant: one thread = 4 packed int32 -> 8 fp16 weights (16B store).
// fused = (absmax1/code1)*(absmax2/code2); w = (q - offset1)*fused; cast fp16.
// ---------------------------------------------------------------------------
__global__ void __launch_bounds__(256) dequant_kernel(
    const int*   __restrict__ packed,
    const int*   __restrict__ absmax1,
    const float* __restrict__ code1,
    const float* __restrict__ offset1,
    const float* __restrict__ absmax2,
    const float* __restrict__ code2)
{
    int t  = blockIdx.x * 256 + threadIdx.x;
    int e0 = t << 3;
    int b1 = e0 >> 6;
    int b2 = e0 >> 8;

    float fused = ((float)absmax1[b1] / code1[b1]) * (absmax2[b2] / code2[b2]);
    float off   = offset1[b1];

    int4 p = ((const int4*)packed)[t];
    int v[4] = {p.x, p.y, p.z, p.w};
    uint32_t r[4];
#pragma unroll
    for (int j = 0; j < 4; j++) {
        float lo = (float)(v[j] & 15);
        float hi = (float)((v[j] >> 4) & 15);
        __half2 h = __floats2half2_rn((lo - off) * fused, (hi - off) * fused);
        r[j] = *reinterpret_cast<uint32_t*>(&h);
    }
    ((uint4*)g_W)[t] = make_uint4(r[0], r[1], r[2], r[3]);
}

// ---------------------------------------------------------------------------
// X convert: fp32 (harness materialization of fp16 data) -> fp16. Exact.
// One thread = 8 elements: 2x float4 load, 1x uint4 store.
// ---------------------------------------------------------------------------
__global__ void __launch_bounds__(256) cvt_x_kernel(const float* __restrict__ xf)
{
    int t = blockIdx.x * 256 + threadIdx.x;
    float4 a = ((const float4*)xf)[2 * t];
    float4 b = ((const float4*)xf)[2 * t + 1];
    __half2 h0 = __floats2half2_rn(a.x, a.y);
    __half2 h1 = __floats2half2_rn(a.z, a.w);
    __half2 h2 = __floats2half2_rn(b.x, b.y);
    __half2 h3 = __floats2half2_rn(b.z, b.w);
    ((uint4*)g_X)[t] = make_uint4(*(uint32_t*)&h0, *(uint32_t*)&h1,
                                  *(uint32_t*)&h2, *(uint32_t*)&h3);
}

// ---------------------------------------------------------------------------
// PTX helpers (family-generic sm_80+: LDGSTS/LDSM/HMMA)
// ---------------------------------------------------------------------------
__device__ __forceinline__ uint32_t smem_u32(const void* p) {
    uint32_t a;
    asm("{ .reg .u64 t; cvta.to.shared.u64 t, %1; cvt.u32.u64 %0, t; }"
        : "=r"(a) : "l"(p));
    return a;
}
__device__ __forceinline__ void cp16(uint32_t s, const void* g) {
    asm volatile("cp.async.cg.shared.global [%0], [%1], 16;" :: "r"(s), "l"(g));
}
__device__ __forceinline__ void cp_commit() {
    asm volatile("cp.async.commit_group;");
}
template <int N> __device__ __forceinline__ void cp_wait() {
    asm volatile("cp.async.wait_group %0;" :: "n"(N));
}
__device__ __forceinline__ void ldm4(uint32_t* r, uint32_t a) {
    asm volatile("ldmatrix.sync.aligned.m8n8.x4.shared.b16 {%0,%1,%2,%3}, [%4];"
                 : "=r"(r[0]), "=r"(r[1]), "=r"(r[2]), "=r"(r[3]) : "r"(a));
}
__device__ __forceinline__ void mma16816(float* d, const uint32_t* a, const uint32_t* b) {
    asm volatile(
        "mma.sync.aligned.m16n8k16.row.col.f32.f16.f16.f32 "
        "{%0,%1,%2,%3}, {%4,%5,%6,%7}, {%8,%9}, {%0,%1,%2,%3};"
        : "+f"(d[0]), "+f"(d[1]), "+f"(d[2]), "+f"(d[3])
        : "r"(a[0]), "r"(a[1]), "r"(a[2]), "r"(a[3]), "r"(b[0]), "r"(b[1]));
}

// smem half-offset of (row, 16B-chunk c) with XOR swizzle; store/load symmetric.
__device__ __forceinline__ uint32_t sw_off(int row, int c) {
    return (uint32_t)(row * CTA_K + ((c ^ ((row >> 1) & 3)) << 3));
}

// fp16 rounding to mirror reference's final .astype(float16)
__device__ __forceinline__ float r16(float v) {
    return __half2float(__float2half_rn(v));
}

// ---------------------------------------------------------------------------
// GEMM: C[8192,11008] (fp32 out) = X[8192,4096] @ W[11008,4096]^T, fp32 acc.
// cp.async 4-stage pipeline, ldmatrix + mma.sync.m16n8k16, 64x64 warp tiles.
// ---------------------------------------------------------------------------
__global__ void __launch_bounds__(256, 1)
gemm_kernel(float* __restrict__ out)
{
    extern __shared__ __half smem[];
    uint32_t sbase = smem_u32(smem);
    int tid = threadIdx.x, lane = tid & 31, wid = tid >> 5;
    int wm = wid >> 2, wn = wid & 3;                 // 2 x 4 warp grid
    int m0 = blockIdx.y * CTA_M;
    int n0 = blockIdx.x * CTA_N;

    auto load_stage = [&](int st, int kblk) {
        uint32_t aB = sbase + st * (A_STAGE_HALFS * 2);
        uint32_t bB = sbase + (NSTAGE * A_STAGE_HALFS + st * B_STAGE_HALFS) * 2;
#pragma unroll
        for (int h = 0; h < 2; h++) {                // A: 512 x 16B
            int id = tid + h * 256;
            int row = id >> 2, c = id & 3;
            const __half* g = g_X + (size_t)(m0 + row) * IN_DIM + kblk + c * 8;
            cp16(aB + sw_off(row, c) * 2, g);
        }
#pragma unroll
        for (int h = 0; h < 4; h++) {                // B: 1024 x 16B
            int id = tid + h * 256;
            int row = id >> 2, c = id & 3;
            const __half* g = g_W + (size_t)(n0 + row) * IN_DIM + kblk + c * 8;
            cp16(bB + sw_off(row, c) * 2, g);
        }
    };

    float acc[4][8][4];
#pragma unroll
    for (int mt = 0; mt < 4; mt++)
#pragma unroll
        for (int nt = 0; nt < 8; nt++)
#pragma unroll
            for (int j = 0; j < 4; j++) acc[mt][nt][j] = 0.0f;

#pragma unroll
    for (int st = 0; st < NSTAGE - 1; st++) {
        load_stage(st, st * CTA_K);
        cp_commit();
    }

    for (int it = 0; it < NK_ITERS; it++) {
        cp_wait<NSTAGE - 2>();
        __syncthreads();

        int nx = it + NSTAGE - 1;
        if (nx < NK_ITERS) load_stage(nx & (NSTAGE - 1), nx * CTA_K);
        cp_commit();

        int st = it & (NSTAGE - 1);
        uint32_t aB = sbase + st * (A_STAGE_HALFS * 2);
        uint32_t bB = sbase + (NSTAGE * A_STAGE_HALFS + st * B_STAGE_HALFS) * 2;

#pragma unroll
        for (int kk = 0; kk < 2; kk++) {
            uint32_t af[4][4], bf[4][4];
#pragma unroll
            for (int mt = 0; mt < 4; mt++) {
                int r = wm * 64 + mt * 16 + (lane & 15);
                int c = kk * 2 + (lane >> 4);
                ldm4(af[mt], aB + sw_off(r, c) * 2);
            }
#pragma unroll
            for (int np = 0; np < 4; np++) {
                int r = wn * 64 + np * 16 + ((lane >> 4) & 1) * 8 + (lane & 7);
                int c = kk * 2 + ((lane >> 3) & 1);
                ldm4(bf[np], bB + sw_off(r, c) * 2);
            }
#pragma unroll
            for (int mt = 0; mt < 4; mt++)
#pragma unroll
                for (int nt = 0; nt < 8; nt++)
                    mma16816(acc[mt][nt], af[mt], &bf[nt >> 1][(nt & 1) * 2]);
        }
    }

    // ---- epilogue: fp32 out, values rounded through fp16 to match reference ----
    int rbase = m0 + wm * 64 + (lane >> 2);
    int cbase = n0 + wn * 64 + (lane & 3) * 2;
#pragma unroll
    for (int mt = 0; mt < 4; mt++)
#pragma unroll
        for (int nt = 0; nt < 8; nt++) {
            int r = rbase + mt * 16, c = cbase + nt * 8;
            *(float2*)(out + (size_t)r * OUT_DIM + c) =
                make_float2(r16(acc[mt][nt][0]), r16(acc[mt][nt][1]));
            *(float2*)(out + (size_t)(r + 8) * OUT_DIM + c) =
                make_float2(r16(acc[mt][nt][2]), r16(acc[mt][nt][3]));
        }
}

// ---------------------------------------------------------------------------
// Host launch
// ---------------------------------------------------------------------------
extern "C" void kernel_launch(void* const* d_in, const int* in_sizes, int n_in,
                              void* d_out, int out_size)
{
    const float* x       = (const float*)d_in[0];   // fp16 data materialized fp32
    const int*   packed  = (const int*)  d_in[1];
    const int*   absmax1 = (const int*)  d_in[2];
    const float* code1   = (const float*)d_in[3];
    const float* offset1 = (const float*)d_in[4];
    const float* absmax2 = (const float*)d_in[5];
    const float* code2   = (const float*)d_in[6];

    dequant_kernel<<<N_ELEM / 8 / 256, 256>>>(packed, absmax1, code1, offset1,
                                              absmax2, code2);
    cvt_x_kernel<<<X_ELEM / 8 / 256, 256>>>(x);

    cudaFuncSetAttribute(gemm_kernel,
                         cudaFuncAttributeMaxDynamicSharedMemorySize, SMEM_BYTES);
    dim3 grid(OUT_DIM / CTA_N, B_DIM / CTA_M);       // (43, 64)
    gemm_kernel<<<grid, 256, SMEM_BYTES>>>((float*)d_out);
}

// round 6
// speedup vs baseline: 1.1271x; 1.1271x over previous
#include <cuda_runtime.h>
#include <cuda_fp16.h>
#include <cstdint>

// ---------------------------------------------------------------------------
// Problem geometry
// ---------------------------------------------------------------------------
#define OUT_DIM 11008
#define IN_DIM  4096
#define B_DIM   8192
#define N_ELEM  (OUT_DIM * IN_DIM)
#define X_ELEM  (B_DIM * IN_DIM)

// GEMM tiling: CTA 128x256, k-stage 64 (128B rows), 8 warps of 64x64
#define CTA_M 128
#define CTA_N 256
#define CTA_K 64
#define NSTAGE 3
#define NK_ITERS (IN_DIM / CTA_K)           // 64

#define A_STAGE_HALFS (CTA_M * CTA_K)       // 8192 halves = 16 KB
#define B_STAGE_HALFS (CTA_N * CTA_K)       // 16384 halves = 32 KB
#define SMEM_BYTES ((A_STAGE_HALFS + B_STAGE_HALFS) * NSTAGE * 2)   // 147456

// ---------------------------------------------------------------------------
// Static device scratch
// ---------------------------------------------------------------------------
__device__ __align__(1024) __half g_W[(size_t)OUT_DIM * IN_DIM];    // 90 MB
__device__ __align__(1024) __half g_X[(size_t)B_DIM * IN_DIM];      // 64 MB

// ---------------------------------------------------------------------------
// Dequant: one thread = 4 packed int32 -> 8 fp16 weights (16B store).
// ---------------------------------------------------------------------------
__global__ void __launch_bounds__(256) dequant_kernel(
    const int*   __restrict__ packed,
    const int*   __restrict__ absmax1,
    const float* __restrict__ code1,
    const float* __restrict__ offset1,
    const float* __restrict__ absmax2,
    const float* __restrict__ code2)
{
    int t  = blockIdx.x * 256 + threadIdx.x;
    int e0 = t << 3;
    int b1 = e0 >> 6;
    int b2 = e0 >> 8;

    float fused = ((float)absmax1[b1] / code1[b1]) * (absmax2[b2] / code2[b2]);
    float off   = offset1[b1];

    int4 p = ((const int4*)packed)[t];
    int v[4] = {p.x, p.y, p.z, p.w};
    uint32_t r[4];
#pragma unroll
    for (int j = 0; j < 4; j++) {
        float lo = (float)(v[j] & 15);
        float hi = (float)((v[j] >> 4) & 15);
        __half2 h = __floats2half2_rn((lo - off) * fused, (hi - off) * fused);
        r[j] = *reinterpret_cast<uint32_t*>(&h);
    }
    ((uint4*)g_W)[t] = make_uint4(r[0], r[1], r[2], r[3]);
}

// ---------------------------------------------------------------------------
// X convert: fp32 (harness materialization of fp16 data) -> fp16. Exact.
// ---------------------------------------------------------------------------
__global__ void __launch_bounds__(256) cvt_x_kernel(const float* __restrict__ xf)
{
    int t = blockIdx.x * 256 + threadIdx.x;
    float4 a = ((const float4*)xf)[2 * t];
    float4 b = ((const float4*)xf)[2 * t + 1];
    __half2 h0 = __floats2half2_rn(a.x, a.y);
    __half2 h1 = __floats2half2_rn(a.z, a.w);
    __half2 h2 = __floats2half2_rn(b.x, b.y);
    __half2 h3 = __floats2half2_rn(b.z, b.w);
    ((uint4*)g_X)[t] = make_uint4(*(uint32_t*)&h0, *(uint32_t*)&h1,
                                  *(uint32_t*)&h2, *(uint32_t*)&h3);
}

// ---------------------------------------------------------------------------
// PTX helpers
// ---------------------------------------------------------------------------
__device__ __forceinline__ uint32_t smem_u32(const void* p) {
    uint32_t a;
    asm("{ .reg .u64 t; cvta.to.shared.u64 t, %1; cvt.u32.u64 %0, t; }"
        : "=r"(a) : "l"(p));
    return a;
}
__device__ __forceinline__ void cp16(uint32_t s, const void* g) {
    asm volatile("cp.async.cg.shared.global [%0], [%1], 16;" :: "r"(s), "l"(g));
}
__device__ __forceinline__ void cp_commit() {
    asm volatile("cp.async.commit_group;");
}
template <int N> __device__ __forceinline__ void cp_wait() {
    asm volatile("cp.async.wait_group %0;" :: "n"(N));
}
__device__ __forceinline__ void ldm4(uint32_t* r, uint32_t a) {
    asm volatile("ldmatrix.sync.aligned.m8n8.x4.shared.b16 {%0,%1,%2,%3}, [%4];"
                 : "=r"(r[0]), "=r"(r[1]), "=r"(r[2]), "=r"(r[3]) : "r"(a));
}
__device__ __forceinline__ void mma16816(float* d, const uint32_t* a, const uint32_t* b) {
    asm volatile(
        "mma.sync.aligned.m16n8k16.row.col.f32.f16.f16.f32 "
        "{%0,%1,%2,%3}, {%4,%5,%6,%7}, {%8,%9}, {%0,%1,%2,%3};"
        : "+f"(d[0]), "+f"(d[1]), "+f"(d[2]), "+f"(d[3])
        : "r"(a[0]), "r"(a[1]), "r"(a[2]), "r"(a[3]), "r"(b[0]), "r"(b[1]));
}

// smem half-offset of (row, 16B-chunk c), 128B rows, 3-bit XOR swizzle.
// Conflict-free for 16B cp.async stores and 8-row ldmatrix phases.
__device__ __forceinline__ uint32_t sw_off(int row, int c) {
    return (uint32_t)(row * CTA_K + ((c ^ (row & 7)) << 3));
}

// fp16 rounding to mirror reference's final .astype(float16)
__device__ __forceinline__ float r16(float v) {
    return __half2float(__float2half_rn(v));
}

// ---------------------------------------------------------------------------
// GEMM: C[8192,11008] (fp32 out) = X @ W^T, fp16 compute, fp32 accum.
// 3-stage cp.async pipeline (k64 stages) + double-buffered fragments.
// ---------------------------------------------------------------------------
__global__ void __launch_bounds__(256, 1)
gemm_kernel(float* __restrict__ out)
{
    extern __shared__ __half smem[];
    uint32_t sbase = smem_u32(smem);
    int tid = threadIdx.x, lane = tid & 31, wid = tid >> 5;
    int wm = wid >> 2, wn = wid & 3;                 // 2 x 4 warp grid
    int m0 = blockIdx.y * CTA_M;
    int n0 = blockIdx.x * CTA_N;

    auto load_stage = [&](int st, int kblk) {
        uint32_t aB = sbase + st * (A_STAGE_HALFS * 2);
        uint32_t bB = sbase + (NSTAGE * A_STAGE_HALFS + st * B_STAGE_HALFS) * 2;
#pragma unroll
        for (int h = 0; h < 4; h++) {                // A: 1024 x 16B chunks
            int id = tid + h * 256;
            int row = id >> 3, c = id & 7;
            const __half* g = g_X + (size_t)(m0 + row) * IN_DIM + kblk + c * 8;
            cp16(aB + sw_off(row, c) * 2, g);
        }
#pragma unroll
        for (int h = 0; h < 8; h++) {                // B: 2048 x 16B chunks
            int id = tid + h * 256;
            int row = id >> 3, c = id & 7;
            const __half* g = g_W + (size_t)(n0 + row) * IN_DIM + kblk + c * 8;
            cp16(bB + sw_off(row, c) * 2, g);
        }
    };

    float acc[4][8][4];
#pragma unroll
    for (int mt = 0; mt < 4; mt++)
#pragma unroll
        for (int nt = 0; nt < 8; nt++)
#pragma unroll
            for (int j = 0; j < 4; j++) acc[mt][nt][j] = 0.0f;

    // fragment double buffers
    uint32_t af[2][4][4], bf[2][4][4];

    auto load_frags = [&](int buf, uint32_t aB, uint32_t bB, int kk) {
#pragma unroll
        for (int mt = 0; mt < 4; mt++) {             // A: 16m x 16k
            int r = wm * 64 + mt * 16 + (lane & 15);
            int c = kk * 2 + (lane >> 4);
            ldm4(af[buf][mt], aB + sw_off(r, c) * 2);
        }
#pragma unroll
        for (int np = 0; np < 4; np++) {             // B: 16n x 16k
            int r = wn * 64 + np * 16 + ((lane >> 4) & 1) * 8 + (lane & 7);
            int c = kk * 2 + ((lane >> 3) & 1);
            ldm4(bf[np == 0 ? buf : buf][np], bB + sw_off(r, c) * 2);  // (indexing below)
        }
    };
    // note: bf is [2][4][4]; fix lambda to index buf properly
    auto load_frags2 = [&](int buf, uint32_t aB, uint32_t bB, int kk) {
#pragma unroll
        for (int mt = 0; mt < 4; mt++) {
            int r = wm * 64 + mt * 16 + (lane & 15);
            int c = kk * 2 + (lane >> 4);
            ldm4(af[buf][mt], aB + sw_off(r, c) * 2);
        }
#pragma unroll
        for (int np = 0; np < 4; np++) {
            int r = wn * 64 + np * 16 + ((lane >> 4) & 1) * 8 + (lane & 7);
            int c = kk * 2 + ((lane >> 3) & 1);
            ldm4(bf[buf][np], bB + sw_off(r, c) * 2);
        }
    };
    (void)load_frags;

    // ---- prologue: fill NSTAGE-1 stages ----
#pragma unroll
    for (int st = 0; st < NSTAGE - 1; st++) {
        load_stage(st, st * CTA_K);
        cp_commit();
    }

    int st = 0;
    // ---- mainloop ----
    for (int it = 0; it < NK_ITERS; it++) {
        cp_wait<NSTAGE - 2>();       // stage `it` resident
        __syncthreads();

        int nx = it + NSTAGE - 1;
        int nst = st + (NSTAGE - 1); if (nst >= NSTAGE) nst -= NSTAGE;
        if (nx < NK_ITERS) load_stage(nst, nx * CTA_K);
        cp_commit();

        uint32_t aB = sbase + st * (A_STAGE_HALFS * 2);
        uint32_t bB = sbase + (NSTAGE * A_STAGE_HALFS + st * B_STAGE_HALFS) * 2;

        load_frags2(0, aB, bB, 0);
#pragma unroll
        for (int kk = 0; kk < 4; kk++) {             // four k16 steps per stage
            int cur = kk & 1;
            if (kk < 3) load_frags2(cur ^ 1, aB, bB, kk + 1);
#pragma unroll
            for (int mt = 0; mt < 4; mt++)
#pragma unroll
                for (int nt = 0; nt < 8; nt++)
                    mma16816(acc[mt][nt], af[cur][mt], &bf[cur][nt >> 1][(nt & 1) * 2]);
        }

        if (++st == NSTAGE) st = 0;
    }

    // ---- epilogue: fp32 out, values rounded through fp16 to match reference ----
    int rbase = m0 + wm * 64 + (lane >> 2);
    int cbase = n0 + wn * 64 + (lane & 3) * 2;
#pragma unroll
    for (int mt = 0; mt < 4; mt++)
#pragma unroll
        for (int nt = 0; nt < 8; nt++) {
            int r = rbase + mt * 16, c = cbase + nt * 8;
            *(float2*)(out + (size_t)r * OUT_DIM + c) =
                make_float2(r16(acc[mt][nt][0]), r16(acc[mt][nt][1]));
            *(float2*)(out + (size_t)(r + 8) * OUT_DIM + c) =
                make_float2(r16(acc[mt][nt][2]), r16(acc[mt][nt][3]));
        }
}

// ---------------------------------------------------------------------------
// Host launch
// ---------------------------------------------------------------------------
extern "C" void kernel_launch(void* const* d_in, const int* in_sizes, int n_in,
                              void* d_out, int out_size)
{
    const float* x       = (const float*)d_in[0];
    const int*   packed  = (const int*)  d_in[1];
    const int*   absmax1 = (const int*)  d_in[2];
    const float* code1   = (const float*)d_in[3];
    const float* offset1 = (const float*)d_in[4];
    const float* absmax2 = (const float*)d_in[5];
    const float* code2   = (const float*)d_in[6];

    dequant_kernel<<<N_ELEM / 8 / 256, 256>>>(packed, absmax1, code1, offset1,
                                              absmax2, code2);
    cvt_x_kernel<<<X_ELEM / 8 / 256, 256>>>(x);

    cudaFuncSetAttribute(gemm_kernel,
                         cudaFuncAttributeMaxDynamicSharedMemorySize, SMEM_BYTES);
    dim3 grid(OUT_DIM / CTA_N, B_DIM / CTA_M);       // (43, 64)
    gemm_kernel<<<grid, 256, SMEM_BYTES>>>((float*)d_out);
}

// round 7
// speedup vs baseline: 1.1355x; 1.0075x over previous
#include <cuda_runtime.h>
#include <cuda_fp16.h>
#include <cstdint>

// ---------------------------------------------------------------------------
// Problem geometry
// ---------------------------------------------------------------------------
#define OUT_DIM 11008
#define IN_DIM  4096
#define B_DIM   8192
#define N_ELEM  (OUT_DIM * IN_DIM)
#define X_ELEM  (B_DIM * IN_DIM)

// GEMM tiling: CTA 128x256, k-stage 64 (128B rows), 16 warps of 32x64
#define CTA_M 128
#define CTA_N 256
#define CTA_K 64
#define NSTAGE 3
#define NTHREADS 512
#define NK_ITERS (IN_DIM / CTA_K)           // 64

#define A_STAGE_HALFS (CTA_M * CTA_K)       // 8192 halves = 16 KB
#define B_STAGE_HALFS (CTA_N * CTA_K)       // 16384 halves = 32 KB
#define SMEM_BYTES ((A_STAGE_HALFS + B_STAGE_HALFS) * NSTAGE * 2)   // 147456

// ---------------------------------------------------------------------------
// Static device scratch
// ---------------------------------------------------------------------------
__device__ __align__(1024) __half g_W[(size_t)OUT_DIM * IN_DIM];    // 90 MB
__device__ __align__(1024) __half g_X[(size_t)B_DIM * IN_DIM];      // 64 MB

// ---------------------------------------------------------------------------
// Dequant: one thread = 4 packed int32 -> 8 fp16 weights (16B store).
// ---------------------------------------------------------------------------
__global__ void __launch_bounds__(256) dequant_kernel(
    const int*   __restrict__ packed,
    const int*   __restrict__ absmax1,
    const float* __restrict__ code1,
    const float* __restrict__ offset1,
    const float* __restrict__ absmax2,
    const float* __restrict__ code2)
{
    int t  = blockIdx.x * 256 + threadIdx.x;
    int e0 = t << 3;
    int b1 = e0 >> 6;
    int b2 = e0 >> 8;

    float fused = ((float)absmax1[b1] / code1[b1]) * (absmax2[b2] / code2[b2]);
    float off   = offset1[b1];

    int4 p = ((const int4*)packed)[t];
    int v[4] = {p.x, p.y, p.z, p.w};
    uint32_t r[4];
#pragma unroll
    for (int j = 0; j < 4; j++) {
        float lo = (float)(v[j] & 15);
        float hi = (float)((v[j] >> 4) & 15);
        __half2 h = __floats2half2_rn((lo - off) * fused, (hi - off) * fused);
        r[j] = *reinterpret_cast<uint32_t*>(&h);
    }
    ((uint4*)g_W)[t] = make_uint4(r[0], r[1], r[2], r[3]);
}

// ---------------------------------------------------------------------------
// X convert: fp32 (harness materialization of fp16 data) -> fp16. Exact.
// ---------------------------------------------------------------------------
__global__ void __launch_bounds__(256) cvt_x_kernel(const float* __restrict__ xf)
{
    int t = blockIdx.x * 256 + threadIdx.x;
    float4 a = ((const float4*)xf)[2 * t];
    float4 b = ((const float4*)xf)[2 * t + 1];
    __half2 h0 = __floats2half2_rn(a.x, a.y);
    __half2 h1 = __floats2half2_rn(a.z, a.w);
    __half2 h2 = __floats2half2_rn(b.x, b.y);
    __half2 h3 = __floats2half2_rn(b.z, b.w);
    ((uint4*)g_X)[t] = make_uint4(*(uint32_t*)&h0, *(uint32_t*)&h1,
                                  *(uint32_t*)&h2, *(uint32_t*)&h3);
}

// ---------------------------------------------------------------------------
// PTX helpers
// ---------------------------------------------------------------------------
__device__ __forceinline__ uint32_t smem_u32(const void* p) {
    uint32_t a;
    asm("{ .reg .u64 t; cvta.to.shared.u64 t, %1; cvt.u32.u64 %0, t; }"
        : "=r"(a) : "l"(p));
    return a;
}
__device__ __forceinline__ void cp16(uint32_t s, const void* g) {
    asm volatile("cp.async.cg.shared.global [%0], [%1], 16;" :: "r"(s), "l"(g));
}
__device__ __forceinline__ void cp_commit() {
    asm volatile("cp.async.commit_group;");
}
template <int N> __device__ __forceinline__ void cp_wait() {
    asm volatile("cp.async.wait_group %0;" :: "n"(N));
}
__device__ __forceinline__ void ldm4(uint32_t* r, uint32_t a) {
    asm volatile("ldmatrix.sync.aligned.m8n8.x4.shared.b16 {%0,%1,%2,%3}, [%4];"
                 : "=r"(r[0]), "=r"(r[1]), "=r"(r[2]), "=r"(r[3]) : "r"(a));
}
__device__ __forceinline__ void mma16816(float* d, const uint32_t* a, const uint32_t* b) {
    asm volatile(
        "mma.sync.aligned.m16n8k16.row.col.f32.f16.f16.f32 "
        "{%0,%1,%2,%3}, {%4,%5,%6,%7}, {%8,%9}, {%0,%1,%2,%3};"
        : "+f"(d[0]), "+f"(d[1]), "+f"(d[2]), "+f"(d[3])
        : "r"(a[0]), "r"(a[1]), "r"(a[2]), "r"(a[3]), "r"(b[0]), "r"(b[1]));
}

// smem half-offset of (row, 16B-chunk c), 128B rows, 3-bit XOR swizzle.
// Conflict-free for 16B cp.async stores and 8-row ldmatrix phases.
__device__ __forceinline__ uint32_t sw_off(int row, int c) {
    return (uint32_t)(row * CTA_K + ((c ^ (row & 7)) << 3));
}

// fp16 rounding to mirror reference's final .astype(float16)
__device__ __forceinline__ float r16(float v) {
    return __half2float(__float2half_rn(v));
}

// ---------------------------------------------------------------------------
// GEMM: C[8192,11008] (fp32 out) = X @ W^T, fp16 compute, fp32 accum.
// 3-stage cp.async pipeline (k64 stages), 16 warps (4 per SMSP) of 32x64.
// ---------------------------------------------------------------------------
__global__ void __launch_bounds__(NTHREADS, 1)
gemm_kernel(float* __restrict__ out)
{
    extern __shared__ __half smem[];
    uint32_t sbase = smem_u32(smem);
    int tid = threadIdx.x, lane = tid & 31, wid = tid >> 5;
    int wm = wid >> 2, wn = wid & 3;                 // 4 x 4 warp grid
    int m0 = blockIdx.y * CTA_M;
    int n0 = blockIdx.x * CTA_N;

    auto load_stage = [&](int st, int kblk) {
        uint32_t aB = sbase + st * (A_STAGE_HALFS * 2);
        uint32_t bB = sbase + (NSTAGE * A_STAGE_HALFS + st * B_STAGE_HALFS) * 2;
#pragma unroll
        for (int h = 0; h < 2; h++) {                // A: 1024 x 16B chunks
            int id = tid + h * NTHREADS;
            int row = id >> 3, c = id & 7;
            const __half* g = g_X + (size_t)(m0 + row) * IN_DIM + kblk + c * 8;
            cp16(aB + sw_off(row, c) * 2, g);
        }
#pragma unroll
        for (int h = 0; h < 4; h++) {                // B: 2048 x 16B chunks
            int id = tid + h * NTHREADS;
            int row = id >> 3, c = id & 7;
            const __half* g = g_W + (size_t)(n0 + row) * IN_DIM + kblk + c * 8;
            cp16(bB + sw_off(row, c) * 2, g);
        }
    };

    float acc[2][8][4];
#pragma unroll
    for (int mt = 0; mt < 2; mt++)
#pragma unroll
        for (int nt = 0; nt < 8; nt++)
#pragma unroll
            for (int j = 0; j < 4; j++) acc[mt][nt][j] = 0.0f;

    // ---- prologue: fill NSTAGE-1 stages ----
#pragma unroll
    for (int st = 0; st < NSTAGE - 1; st++) {
        load_stage(st, st * CTA_K);
        cp_commit();
    }

    int st = 0;
    for (int it = 0; it < NK_ITERS; it++) {
        cp_wait<NSTAGE - 2>();       // stage `it` resident
        __syncthreads();

        int nx = it + NSTAGE - 1;
        int nst = st + (NSTAGE - 1); if (nst >= NSTAGE) nst -= NSTAGE;
        if (nx < NK_ITERS) load_stage(nst, nx * CTA_K);
        cp_commit();

        uint32_t aB = sbase + st * (A_STAGE_HALFS * 2);
        uint32_t bB = sbase + (NSTAGE * A_STAGE_HALFS + st * B_STAGE_HALFS) * 2;

#pragma unroll
        for (int kk = 0; kk < 4; kk++) {             // four k16 steps per stage
            uint32_t af[2][4], bf[4][4];
#pragma unroll
            for (int mt = 0; mt < 2; mt++) {         // A: 16m x 16k
                int r = wm * 32 + mt * 16 + (lane & 15);
                int c = kk * 2 + (lane >> 4);
                ldm4(af[mt], aB + sw_off(r, c) * 2);
            }
#pragma unroll
            for (int np = 0; np < 4; np++) {         // B: 16n x 16k
                int r = wn * 64 + np * 16 + ((lane >> 4) & 1) * 8 + (lane & 7);
                int c = kk * 2 + ((lane >> 3) & 1);
                ldm4(bf[np], bB + sw_off(r, c) * 2);
            }
#pragma unroll
            for (int mt = 0; mt < 2; mt++)
#pragma unroll
                for (int nt = 0; nt < 8; nt++)
                    mma16816(acc[mt][nt], af[mt], &bf[nt >> 1][(nt & 1) * 2]);
        }

        if (++st == NSTAGE) st = 0;
    }

    // ---- epilogue: fp32 out, values rounded through fp16 to match reference ----
    int rbase = m0 + wm * 32 + (lane >> 2);
    int cbase = n0 + wn * 64 + (lane & 3) * 2;
#pragma unroll
    for (int mt = 0; mt < 2; mt++)
#pragma unroll
        for (int nt = 0; nt < 8; nt++) {
            int r = rbase + mt * 16, c = cbase + nt * 8;
            *(float2*)(out + (size_t)r * OUT_DIM + c) =
                make_float2(r16(acc[mt][nt][0]), r16(acc[mt][nt][1]));
            *(float2*)(out + (size_t)(r + 8) * OUT_DIM + c) =
                make_float2(r16(acc[mt][nt][2]), r16(acc[mt][nt][3]));
        }
}

// ---------------------------------------------------------------------------
// Host launch
// ---------------------------------------------------------------------------
extern "C" void kernel_launch(void* const* d_in, const int* in_sizes, int n_in,
                              void* d_out, int out_size)
{
    const float* x       = (const float*)d_in[0];
    const int*   packed  = (const int*)  d_in[1];
    const int*   absmax1 = (const int*)  d_in[2];
    const float* code1   = (const float*)d_in[3];
    const float* offset1 = (const float*)d_in[4];
    const float* absmax2 = (const float*)d_in[5];
    const float* code2   = (const float*)d_in[6];

    dequant_kernel<<<N_ELEM / 8 / 256, 256>>>(packed, absmax1, code1, offset1,
                                              absmax2, code2);
    cvt_x_kernel<<<X_ELEM / 8 / 256, 256>>>(x);

    cudaFuncSetAttribute(gemm_kernel,
                         cudaFuncAttributeMaxDynamicSharedMemorySize, SMEM_BYTES);
    dim3 grid(OUT_DIM / CTA_N, B_DIM / CTA_M);       // (43, 64)
    gemm_kernel<<<grid, NTHREADS, SMEM_BYTES>>>((float*)d_out);
}

// round 12
// speedup vs baseline: 1.1644x; 1.0254x over previous
#include <cuda_runtime.h>
#include <cuda_fp16.h>
#include <cstdint>

// ---------------------------------------------------------------------------
// Problem geometry
// ---------------------------------------------------------------------------
#define OUT_DIM 11008
#define IN_DIM  4096
#define B_DIM   8192
#define N_ELEM  (OUT_DIM * IN_DIM)
#define X_ELEM  (B_DIM * IN_DIM)
#define W_BLOCKS (N_ELEM / 8 / 256)         // 22016
#define X_BLOCKS (X_ELEM / 8 / 256)         // 16384

// GEMM tiling: CTA 128x256, k-stage 128 (256B rows), 16 warps of 32x64
#define CTA_M 128
#define CTA_N 256
#define CTA_K 128
#define NSTAGE 2
#define NTHREADS 512
#define NK_ITERS (IN_DIM / CTA_K)           // 32

#define A_BYTES (CTA_M * CTA_K * 2)         // 32768
#define B_BYTES (CTA_N * CTA_K * 2)         // 65536
#define STAGE_BYTES (A_BYTES + B_BYTES)     // 98304
#define SMEM_BYTES (NSTAGE * STAGE_BYTES)   // 196608 (fits 227KB)

// ---------------------------------------------------------------------------
// Static device scratch (row-major, proven layout)
// ---------------------------------------------------------------------------
__device__ __align__(1024) __half g_W[(size_t)OUT_DIM * IN_DIM];    // 90 MB
__device__ __align__(1024) __half g_X[(size_t)B_DIM * IN_DIM];      // 64 MB

// ---------------------------------------------------------------------------
// Prep: fused W-dequant + X fp32->fp16 convert (proven in R7).
// ---------------------------------------------------------------------------
__global__ void __launch_bounds__(256) prep_kernel(
    const int*   __restrict__ packed,
    const int*   __restrict__ absmax1,
    const float* __restrict__ code1,
    const float* __restrict__ offset1,
    const float* __restrict__ absmax2,
    const float* __restrict__ code2,
    const float* __restrict__ xf)
{
    int b = blockIdx.x;
    if (b < W_BLOCKS) {
        int t  = b * 256 + threadIdx.x;
        int e0 = t << 3;
        int b1 = e0 >> 6;
        int b2 = e0 >> 8;
        float fused = ((float)absmax1[b1] / code1[b1]) * (absmax2[b2] / code2[b2]);
        float off   = offset1[b1];
        int4 p = ((const int4*)packed)[t];
        int v[4] = {p.x, p.y, p.z, p.w};
        uint32_t r[4];
#pragma unroll
        for (int j = 0; j < 4; j++) {
            float lo = (float)(v[j] & 15);
            float hi = (float)((v[j] >> 4) & 15);
            __half2 h = __floats2half2_rn((lo - off) * fused, (hi - off) * fused);
            r[j] = *reinterpret_cast<uint32_t*>(&h);
        }
        ((uint4*)g_W)[t] = make_uint4(r[0], r[1], r[2], r[3]);
    } else {
        int t = (b - W_BLOCKS) * 256 + threadIdx.x;
        float4 a = ((const float4*)xf)[2 * t];
        float4 c = ((const float4*)xf)[2 * t + 1];
        __half2 h0 = __floats2half2_rn(a.x, a.y);
        __half2 h1 = __floats2half2_rn(a.z, a.w);
        __half2 h2 = __floats2half2_rn(c.x, c.y);
        __half2 h3 = __floats2half2_rn(c.z, c.w);
        ((uint4*)g_X)[t] = make_uint4(*(uint32_t*)&h0, *(uint32_t*)&h1,
                                      *(uint32_t*)&h2, *(uint32_t*)&h3);
    }
}

// ---------------------------------------------------------------------------
// PTX helpers (only the proven family: LDGSTS / LDSM / HMMA)
// ---------------------------------------------------------------------------
__device__ __forceinline__ uint32_t smem_u32(const void* p) {
    uint32_t a;
    asm("{ .reg .u64 t; cvta.to.shared.u64 t, %1; cvt.u32.u64 %0, t; }"
        : "=r"(a) : "l"(p));
    return a;
}
__device__ __forceinline__ void cp16(uint32_t s, const void* g) {
    asm volatile("cp.async.cg.shared.global [%0], [%1], 16;" :: "r"(s), "l"(g));
}
__device__ __forceinline__ void cp_commit() {
    asm volatile("cp.async.commit_group;");
}
template <int N> __device__ __forceinline__ void cp_wait() {
    asm volatile("cp.async.wait_group %0;" :: "n"(N));
}
__device__ __forceinline__ void ldm4(uint32_t* r, uint32_t a) {
    asm volatile("ldmatrix.sync.aligned.m8n8.x4.shared.b16 {%0,%1,%2,%3}, [%4];"
                 : "=r"(r[0]), "=r"(r[1]), "=r"(r[2]), "=r"(r[3]) : "r"(a));
}
__device__ __forceinline__ void mma16816(float* d, const uint32_t* a, const uint32_t* b) {
    asm volatile(
        "mma.sync.aligned.m16n8k16.row.col.f32.f16.f16.f32 "
        "{%0,%1,%2,%3}, {%4,%5,%6,%7}, {%8,%9}, {%0,%1,%2,%3};"
        : "+f"(d[0]), "+f"(d[1]), "+f"(d[2]), "+f"(d[3])
        : "r"(a[0]), "r"(a[1]), "r"(a[2]), "r"(a[3]), "r"(b[0]), "r"(b[1]));
}

// smem half-offset of (row, 16B-chunk c) for 256B rows (16 chunks/row).
// XOR on low 3 bits of c: ldmatrix 8-row phases hit 8 distinct banks;
// cp.async 16B stores stay conflict-free (bijection within each half-row).
__device__ __forceinline__ uint32_t sw_off(int row, int c) {
    return (uint32_t)(row * CTA_K + ((c ^ (row & 7)) << 3));
}
__device__ __forceinline__ float r16(float v) {
    return __half2float(__float2half_rn(v));
}

// ---------------------------------------------------------------------------
// Consumer core (identical math to the passing R7 kernel; kk now spans [0,8))
// ---------------------------------------------------------------------------
struct Frags { uint32_t af[2][4]; uint32_t bf[4][4]; };

__device__ __forceinline__ void load_frags(Frags& f, uint32_t aB, uint32_t bB,
                                           int kk, int wm, int wn, int lane) {
#pragma unroll
    for (int mt = 0; mt < 2; mt++) {
        int r = wm * 32 + mt * 16 + (lane & 15);
        int c = kk * 2 + (lane >> 4);
        ldm4(f.af[mt], aB + sw_off(r, c) * 2);
    }
#pragma unroll
    for (int np = 0; np < 4; np++) {
        int r = wn * 64 + np * 16 + ((lane >> 4) & 1) * 8 + (lane & 7);
        int c = kk * 2 + ((lane >> 3) & 1);
        ldm4(f.bf[np], bB + sw_off(r, c) * 2);
    }
}

__device__ __forceinline__ void do_mmas(float acc[2][8][4], const Frags& f) {
#pragma unroll
    for (int mt = 0; mt < 2; mt++)
#pragma unroll
        for (int nt = 0; nt < 8; nt++)
            mma16816(acc[mt][nt], f.af[mt], &f.bf[nt >> 1][(nt & 1) * 2]);
}

// ---------------------------------------------------------------------------
// GEMM: C[8192,11008] (fp32 out) = X @ W^T, fp16 compute, fp32 accum.
// 2-stage k128 cp.async pipeline: 32 barriers instead of 64; 8 k16 steps
// of uninterrupted MMA issue per stage. Prefetch overlaps compute.
// ---------------------------------------------------------------------------
__global__ void __launch_bounds__(NTHREADS, 1)
gemm_kernel(float* __restrict__ out)
{
    extern __shared__ __align__(1024) char smem[];
    uint32_t sbase = smem_u32(smem);
    int tid = threadIdx.x, lane = tid & 31, wid = tid >> 5;
    int wm = wid >> 2, wn = wid & 3;                 // 4 x 4 warp grid
    int m0 = blockIdx.y * CTA_M;
    int n0 = blockIdx.x * CTA_N;

    // stage loader: A = 2048 chunks (4/thread), B = 4096 chunks (8/thread)
    auto load_stage = [&](int st, int kblk) {
        uint32_t aB = sbase + st * STAGE_BYTES;
        uint32_t bB = aB + A_BYTES;
#pragma unroll
        for (int h = 0; h < 4; h++) {
            int id = tid + h * NTHREADS;
            int row = id >> 4, c = id & 15;          // 16 chunks per 256B row
            const __half* g = g_X + (size_t)(m0 + row) * IN_DIM + kblk + c * 8;
            cp16(aB + sw_off(row, c) * 2, g);
        }
#pragma unroll
        for (int h = 0; h < 8; h++) {
            int id = tid + h * NTHREADS;
            int row = id >> 4, c = id & 15;
            const __half* g = g_W + (size_t)(n0 + row) * IN_DIM + kblk + c * 8;
            cp16(bB + sw_off(row, c) * 2, g);
        }
    };

    float acc[2][8][4];
#pragma unroll
    for (int mt = 0; mt < 2; mt++)
#pragma unroll
        for (int nt = 0; nt < 8; nt++)
#pragma unroll
            for (int j = 0; j < 4; j++) acc[mt][nt][j] = 0.0f;

    // prologue: stage 0 in flight
    load_stage(0, 0);
    cp_commit();

    Frags fr[2];
    for (int it = 0; it < NK_ITERS; it++) {
        cp_wait<0>();                 // stage `it` resident (only pending group)
        __syncthreads();              // all warps past wait AND done with prev buf

        // prefetch next stage into the buffer freed by iteration it-1;
        // overlaps with the 8 k16 compute steps below (~full stage of cover)
        int nx = it + 1;
        if (nx < NK_ITERS) {
            load_stage(nx & 1, nx * CTA_K);
            cp_commit();
        }

        uint32_t aB = sbase + (it & 1) * STAGE_BYTES;
        uint32_t bB = aB + A_BYTES;

        load_frags(fr[0], aB, bB, 0, wm, wn, lane);
#pragma unroll
        for (int kk = 0; kk < 8; kk++) {             // eight k16 steps per stage
            int cur = kk & 1;
            if (kk < 7) load_frags(fr[cur ^ 1], aB, bB, kk + 1, wm, wn, lane);
            do_mmas(acc, fr[cur]);
        }
    }

    // ---- epilogue: fp32 out, values rounded through fp16 to match reference ----
    int rbase = m0 + wm * 32 + (lane >> 2);
    int cbase = n0 + wn * 64 + (lane & 3) * 2;
#pragma unroll
    for (int mt = 0; mt < 2; mt++)
#pragma unroll
        for (int nt = 0; nt < 8; nt++) {
            int r = rbase + mt * 16, c = cbase + nt * 8;
            *(float2*)(out + (size_t)r * OUT_DIM + c) =
                make_float2(r16(acc[mt][nt][0]), r16(acc[mt][nt][1]));
            *(float2*)(out + (size_t)(r + 8) * OUT_DIM + c) =
                make_float2(r16(acc[mt][nt][2]), r16(acc[mt][nt][3]));
        }
}

// ---------------------------------------------------------------------------
// Host launch: runtime API only (proven path).
// ---------------------------------------------------------------------------
extern "C" void kernel_launch(void* const* d_in, const int* in_sizes, int n_in,
                              void* d_out, int out_size)
{
    const float* x       = (const float*)d_in[0];
    const int*   packed  = (const int*)  d_in[1];
    const int*   absmax1 = (const int*)  d_in[2];
    const float* code1   = (const float*)d_in[3];
    const float* offset1 = (const float*)d_in[4];
    const float* absmax2 = (const float*)d_in[5];
    const float* code2   = (const float*)d_in[6];

    prep_kernel<<<W_BLOCKS + X_BLOCKS, 256>>>(packed, absmax1, code1, offset1,
                                              absmax2, code2, x);

    cudaFuncSetAttribute(gemm_kernel,
                         cudaFuncAttributeMaxDynamicSharedMemorySize, SMEM_BYTES);
    dim3 grid(OUT_DIM / CTA_N, B_DIM / CTA_M);       // (43, 64)
    gemm_kernel<<<grid, NTHREADS, SMEM_BYTES>>>((float*)d_out);
}